// round 1
// baseline (speedup 1.0000x reference)
#include <cuda_runtime.h>
#include <math.h>

#define B_   16
#define N_   4096
#define C_   1152
#define H_   16
#define HD_  72
#define KV2  144          // 2*HD
#define NCAT 1296         // C_ + KV2
#define MTOT (B_*N_)      // 65536

// ---------------- scratch (static device globals; no runtime alloc) -------
__device__ float g_q[(size_t)MTOT * C_];        // 302 MB  q = x@wq + b
__device__ float g_kvlin[(size_t)MTOT * KV2];   // 37.7 MB [k|v]
__device__ float g_vd[(size_t)MTOT * HD_];      // 18.9 MB depthwise conv out
__device__ float g_kv[B_ * HD_ * HD_];          // kv = k_f^T @ v  (per batch)
__device__ float g_M[(size_t)B_ * C_ * C_];     // 85 MB  blockdiag(kv)@proj
__device__ float g_projsum[HD_ * C_];           // sum_h proj rows
__device__ float g_qsum[B_ * H_ * 2];           // {sum r^2, sum r^6} per (b,h)
__device__ float g_ksum[B_ * 2];                // per b
__device__ float g_scaleq[B_ * H_];
__device__ float g_scalek[B_];

// ---------------- init: zero accumulators ---------------------------------
__global__ void k_init() {
    int i = blockIdx.x * blockDim.x + threadIdx.x;
    if (i < B_ * HD_ * HD_) g_kv[i] = 0.f;
    if (i < B_ * H_ * 2)    g_qsum[i] = 0.f;
    if (i < B_ * 2)         g_ksum[i] = 0.f;
}

// ---------------- shared GEMM micro-kernel --------------------------------
template <int KK>
__device__ __forceinline__ void mma_tile(const float As[16][132],
                                         const float Bs[16][128],
                                         float (&acc)[8][8], int ty, int tx) {
#pragma unroll
    for (int k = 0; k < KK; k++) {
        float4 a0 = *(const float4*)&As[k][ty * 8];
        float4 a1 = *(const float4*)&As[k][ty * 8 + 4];
        float4 b0 = *(const float4*)&Bs[k][tx * 8];
        float4 b1 = *(const float4*)&Bs[k][tx * 8 + 4];
        float a[8] = {a0.x, a0.y, a0.z, a0.w, a1.x, a1.y, a1.z, a1.w};
        float b[8] = {b0.x, b0.y, b0.z, b0.w, b1.x, b1.y, b1.z, b1.w};
#pragma unroll
        for (int i = 0; i < 8; i++)
#pragma unroll
            for (int j = 0; j < 8; j++) acc[i][j] += a[i] * b[j];
    }
}

// ---------------- GEMM1: Y = x @ [wq | wkv] + bias ------------------------
// grid (11, 512), block 256.  Writes q part -> g_q, kv part -> g_kvlin.
__global__ __launch_bounds__(256) void k_gemm1(
    const float* __restrict__ x,
    const float* __restrict__ wq,  const float* __restrict__ wqb,
    const float* __restrict__ wkv, const float* __restrict__ wkvb) {
    __shared__ float As[16][132];
    __shared__ float Bs[16][128];
    int tid = threadIdx.x;
    int m0 = blockIdx.y * 128;
    int n0 = blockIdx.x * 128;
    int tx = tid & 15, ty = tid >> 4;
    float acc[8][8] = {};

    for (int kt = 0; kt < C_; kt += 16) {
#pragma unroll
        for (int e = tid; e < 2048; e += 256) {
            int r = e >> 4, kk = e & 15;
            As[kk][r] = x[(size_t)(m0 + r) * C_ + kt + kk];
        }
#pragma unroll
        for (int e = tid; e < 2048; e += 256) {
            int kk = e >> 7, cc = e & 127;
            int n = n0 + cc;
            float bv;
            if (n < C_)         bv = wq[(size_t)(kt + kk) * C_ + n];
            else if (n < NCAT)  bv = wkv[(size_t)(kt + kk) * KV2 + (n - C_)];
            else                bv = 0.f;
            Bs[kk][cc] = bv;
        }
        __syncthreads();
        mma_tile<16>(As, Bs, acc, ty, tx);
        __syncthreads();
    }

#pragma unroll
    for (int i = 0; i < 8; i++) {
        int m = m0 + ty * 8 + i;
#pragma unroll
        for (int j = 0; j < 8; j++) {
            int n = n0 + tx * 8 + j;
            float v = acc[i][j];
            if (n < C_)
                g_q[(size_t)m * C_ + n] = v + wqb[n];
            else if (n < NCAT)
                g_kvlin[(size_t)m * KV2 + (n - C_)] = v + wkvb[n - C_];
        }
    }
}

// ---------------- block reduce two floats ----------------------------------
__device__ __forceinline__ void block_reduce2(float& s2, float& s6) {
#pragma unroll
    for (int o = 16; o; o >>= 1) {
        s2 += __shfl_down_sync(0xffffffffu, s2, o);
        s6 += __shfl_down_sync(0xffffffffu, s6, o);
    }
    __shared__ float sh2[8], sh6[8];
    int w = threadIdx.x >> 5, l = threadIdx.x & 31;
    if (l == 0) { sh2[w] = s2; sh6[w] = s6; }
    __syncthreads();
    if (threadIdx.x == 0) {
        float a = 0.f, c = 0.f;
#pragma unroll
        for (int i = 0; i < 8; i++) { a += sh2[i]; c += sh6[i]; }
        s2 = a; s6 = c;
    }
}

// ---------------- focused-norm reductions ----------------------------------
// grid 4096 = (bh 256) x (split 16); block 256
__global__ void k_qnorm() {
    int bh = blockIdx.x >> 4;
    int split = blockIdx.x & 15;
    int b = bh >> 4, h = bh & 15;
    const float* base = g_q + (size_t)(b * N_ + split * 256) * C_ + h * HD_;
    float s2 = 0.f, s6 = 0.f;
    for (int e = threadIdx.x; e < 256 * HD_; e += 256) {
        int r = e / HD_, d = e % HD_;
        float v = base[(size_t)r * C_ + d];
        float rr = fmaxf(v, 0.f);
        float r2 = rr * rr;  s2 += r2;
        float r3 = r2 * rr;  s6 += r3 * r3;
    }
    block_reduce2(s2, s6);
    if (threadIdx.x == 0) {
        atomicAdd(&g_qsum[bh * 2], s2);
        atomicAdd(&g_qsum[bh * 2 + 1], s6);
    }
}

// grid 256 = (b 16) x (split 16); block 256
__global__ void k_knorm() {
    int b = blockIdx.x >> 4;
    int split = blockIdx.x & 15;
    const float* base = g_kvlin + (size_t)(b * N_ + split * 256) * KV2;
    float s2 = 0.f, s6 = 0.f;
    for (int e = threadIdx.x; e < 256 * HD_; e += 256) {
        int r = e / HD_, d = e % HD_;
        float v = base[(size_t)r * KV2 + d];
        float rr = fmaxf(v, 0.f);
        float r2 = rr * rr;  s2 += r2;
        float r3 = r2 * rr;  s6 += r3 * r3;
    }
    block_reduce2(s2, s6);
    if (threadIdx.x == 0) {
        atomicAdd(&g_ksum[b * 2], s2);
        atomicAdd(&g_ksum[b * 2 + 1], s6);
    }
}

__global__ void k_scales() {
    int i = threadIdx.x;
    if (i < B_ * H_) {
        float s2 = g_qsum[i * 2], s6 = g_qsum[i * 2 + 1];
        g_scaleq[i] = (s6 > 0.f) ? sqrtf(s2 / s6) : 0.f;
    } else if (i < B_ * H_ + B_) {
        int b = i - B_ * H_;
        float s2 = g_ksum[b * 2], s6 = g_ksum[b * 2 + 1];
        g_scalek[b] = (s6 > 0.f) ? sqrtf(s2 / s6) : 0.f;
    }
}

// ---------------- kv = k_f^T @ v (per batch) --------------------------------
// grid (8 nsplits, 16 b), block 576; each thread owns 9 of 5184 outputs
__global__ __launch_bounds__(576) void k_kvacc() {
    __shared__ float ks[16][72], vs[16][72];
    int b = blockIdx.y;
    int n0 = blockIdx.x * 512;
    int tid = threadIdx.x;
    float acc[9] = {};
    int od[9], oe[9];
#pragma unroll
    for (int j = 0; j < 9; j++) { int o = tid + j * 576; od[j] = o / 72; oe[j] = o % 72; }

    for (int nt = 0; nt < 512; nt += 16) {
        __syncthreads();
        for (int e = tid; e < 16 * 72; e += 576) {
            int r = e / 72, d = e % 72;
            const float* p = g_kvlin + (size_t)(b * N_ + n0 + nt + r) * KV2;
            float kvv = p[d];
            float rr = fmaxf(kvv, 0.f);
            ks[r][d] = rr * rr * rr;
            vs[r][d] = p[72 + d];
        }
        __syncthreads();
#pragma unroll
        for (int r = 0; r < 16; r++)
#pragma unroll
            for (int j = 0; j < 9; j++) acc[j] += ks[r][od[j]] * vs[r][oe[j]];
    }
    float s = g_scalek[b];
#pragma unroll
    for (int j = 0; j < 9; j++)
        atomicAdd(&g_kv[b * 5184 + tid + j * 576], acc[j] * s);
}

// ---------------- depthwise 3x3 conv on v -----------------------------------
// grid 18432, block 256 (one thread per output element)
__global__ void k_dwc(const float* __restrict__ w, const float* __restrict__ bias) {
    int idx = blockIdx.x * blockDim.x + threadIdx.x;
    int d = idx % HD_;
    int t = idx / HD_;
    int n = t % N_;
    int b = t / N_;
    int y = n >> 6, xx = n & 63;
    float acc = bias[d];
#pragma unroll
    for (int ky = 0; ky < 3; ky++) {
        int yy = y + ky - 1;
        if ((unsigned)yy < 64u) {
#pragma unroll
            for (int kx = 0; kx < 3; kx++) {
                int xc = xx + kx - 1;
                if ((unsigned)xc < 64u)
                    acc += g_kvlin[(size_t)(b * N_ + yy * 64 + xc) * KV2 + 72 + d]
                         * w[d * 9 + ky * 3 + kx];
            }
        }
    }
    g_vd[(size_t)(b * N_ + n) * HD_ + d] = acc;
}

// ---------------- proj_sum[d][c] = sum_h proj[h*72+d][c] --------------------
// grid 324, block 256
__global__ void k_projsum(const float* __restrict__ proj) {
    int idx = blockIdx.x * blockDim.x + threadIdx.x;
    if (idx >= HD_ * C_) return;
    int d = idx / C_, c = idx % C_;
    float s = 0.f;
#pragma unroll
    for (int h = 0; h < H_; h++) s += proj[(size_t)(h * HD_ + d) * C_ + c];
    g_projsum[(size_t)d * C_ + c] = s;
}

// ---------------- M[b][h*72+d][c] = sum_e kv[b][d][e] * proj[h*72+e][c] -----
// grid (9 ctiles, 16 h, 16 b), block 256
__global__ __launch_bounds__(256) void k_mker(const float* __restrict__ proj) {
    __shared__ float kvs[72 * 72];
    int b = blockIdx.z, h = blockIdx.y, ct = blockIdx.x;
    int tid = threadIdx.x;
    for (int e = tid; e < 5184; e += 256) kvs[e] = g_kv[b * 5184 + e];
    __syncthreads();
    int c = ct * 128 + (tid & 127);
    int dbase = (tid >> 7) * 36;
    float acc[36] = {};
#pragma unroll 8
    for (int e2 = 0; e2 < 72; e2++) {
        float p = proj[(size_t)(h * HD_ + e2) * C_ + c];
#pragma unroll
        for (int dd = 0; dd < 36; dd++)
            acc[dd] += kvs[(dbase + dd) * 72 + e2] * p;
    }
#pragma unroll
    for (int dd = 0; dd < 36; dd++)
        g_M[(size_t)b * C_ * C_ + (size_t)(h * HD_ + dbase + dd) * C_ + c] = acc[dd];
}

// ---------------- GEMM2: out[b] = focused(q)[b]@M[b] + vd[b]@proj_sum + bias -
// grid (9, 32, 16), block 256
__global__ __launch_bounds__(256) void k_gemm2(const float* __restrict__ projb,
                                               float* __restrict__ out) {
    __shared__ float As[16][132];
    __shared__ float Bs[16][128];
    __shared__ float sq[16];
    int tid = threadIdx.x;
    int b = blockIdx.z;
    int m0 = blockIdx.y * 128;
    int n0 = blockIdx.x * 128;
    int tx = tid & 15, ty = tid >> 4;
    if (tid < 16) sq[tid] = g_scaleq[b * H_ + tid];
    __syncthreads();

    const float* qb = g_q + (size_t)b * N_ * C_;
    const float* Mb = g_M + (size_t)b * C_ * C_;
    float acc[8][8] = {};

    // phase 1: K = 1152 over focused(q) @ M[b]
    for (int kt = 0; kt < C_; kt += 16) {
#pragma unroll
        for (int e = tid; e < 2048; e += 256) {
            int r = e >> 4, kk = e & 15;
            int gk = kt + kk;
            int h = gk / 72;
            float v = qb[(size_t)(m0 + r) * C_ + gk];
            float rr = fmaxf(v, 0.f);
            As[kk][r] = sq[h] * rr * rr * rr;
        }
#pragma unroll
        for (int e = tid; e < 2048; e += 256) {
            int kk = e >> 7, cc = e & 127;
            Bs[kk][cc] = Mb[(size_t)(kt + kk) * C_ + n0 + cc];
        }
        __syncthreads();
        mma_tile<16>(As, Bs, acc, ty, tx);
        __syncthreads();
    }

    // phase 2: K = 72 over vd @ proj_sum
    const float* vdb = g_vd + (size_t)b * N_ * HD_;
    for (int kt = 0; kt < HD_; kt += 8) {
#pragma unroll
        for (int e = tid; e < 1024; e += 256) {
            int r = e >> 3, kk = e & 7;
            As[kk][r] = vdb[(size_t)(m0 + r) * HD_ + kt + kk];
        }
#pragma unroll
        for (int e = tid; e < 1024; e += 256) {
            int kk = e >> 7, cc = e & 127;
            Bs[kk][cc] = g_projsum[(size_t)(kt + kk) * C_ + n0 + cc];
        }
        __syncthreads();
        mma_tile<8>(As, Bs, acc, ty, tx);
        __syncthreads();
    }

#pragma unroll
    for (int i = 0; i < 8; i++) {
        int m = m0 + ty * 8 + i;
#pragma unroll
        for (int j = 0; j < 8; j++) {
            int n = n0 + tx * 8 + j;
            out[(size_t)(b * N_ + m) * C_ + n] = acc[i][j] + projb[n];
        }
    }
}

// ---------------- launch -----------------------------------------------------
extern "C" void kernel_launch(void* const* d_in, const int* in_sizes, int n_in,
                              void* d_out, int out_size) {
    const float* x      = (const float*)d_in[0];
    const float* wq_w   = (const float*)d_in[1];
    const float* wq_b   = (const float*)d_in[2];
    const float* wkv_w  = (const float*)d_in[3];
    const float* wkv_b  = (const float*)d_in[4];
    const float* dwc_w  = (const float*)d_in[5];
    const float* dwc_b  = (const float*)d_in[6];
    const float* proj_w = (const float*)d_in[7];
    const float* proj_b = (const float*)d_in[8];
    float* out = (float*)d_out;

    k_init<<<324, 256>>>();
    k_gemm1<<<dim3(11, 512), 256>>>(x, wq_w, wq_b, wkv_w, wkv_b);
    k_qnorm<<<4096, 256>>>();
    k_knorm<<<256, 256>>>();
    k_scales<<<1, 288>>>();
    k_kvacc<<<dim3(8, 16), 576>>>();
    k_dwc<<<18432, 256>>>(dwc_w, dwc_b);
    k_projsum<<<324, 256>>>(proj_w);
    k_mker<<<dim3(9, 16, 16), 256>>>(proj_w);
    k_gemm2<<<dim3(9, 32, 16), 256>>>(proj_b, out);
}

// round 2
// speedup vs baseline: 1.0005x; 1.0005x over previous
#include <cuda_runtime.h>
#include <math.h>

#define B_   16
#define N_   4096
#define C_   1152
#define H_   16
#define HD_  72
#define KV2  144          // 2*HD
#define NCAT 1296         // C_ + KV2
#define MTOT (B_*N_)      // 65536

// ---------------- scratch (static device globals; no runtime alloc) -------
__device__ float g_q[(size_t)MTOT * C_];        // 302 MB  q = x@wq + b
__device__ float g_kvlin[(size_t)MTOT * KV2];   // 37.7 MB [k|v]
__device__ float g_vd[(size_t)MTOT * HD_];      // 18.9 MB depthwise conv out
__device__ float g_kv[B_ * HD_ * HD_];          // kv = k_f^T @ v  (per batch)
__device__ float g_M[(size_t)B_ * C_ * C_];     // 85 MB  blockdiag(kv)@proj
__device__ float g_projsum[HD_ * C_];           // sum_h proj rows
__device__ float g_qsum[B_ * H_ * 2];           // {sum r^2, sum r^6} per (b,h)
__device__ float g_ksum[B_ * 2];                // per b
__device__ float g_scaleq[B_ * H_];
__device__ float g_scalek[B_];

// ---------------- init: zero accumulators ---------------------------------
__global__ void k_init() {
    int i = blockIdx.x * blockDim.x + threadIdx.x;
    if (i < B_ * HD_ * HD_) g_kv[i] = 0.f;
    if (i < B_ * H_ * 2)    g_qsum[i] = 0.f;
    if (i < B_ * 2)         g_ksum[i] = 0.f;
}

// ---------------- shared GEMM micro-kernel --------------------------------
template <int KK>
__device__ __forceinline__ void mma_tile(const float As[16][132],
                                         const float Bs[16][128],
                                         float (&acc)[8][8], int ty, int tx) {
#pragma unroll
    for (int k = 0; k < KK; k++) {
        float4 a0 = *(const float4*)&As[k][ty * 8];
        float4 a1 = *(const float4*)&As[k][ty * 8 + 4];
        float4 b0 = *(const float4*)&Bs[k][tx * 8];
        float4 b1 = *(const float4*)&Bs[k][tx * 8 + 4];
        float a[8] = {a0.x, a0.y, a0.z, a0.w, a1.x, a1.y, a1.z, a1.w};
        float b[8] = {b0.x, b0.y, b0.z, b0.w, b1.x, b1.y, b1.z, b1.w};
#pragma unroll
        for (int i = 0; i < 8; i++)
#pragma unroll
            for (int j = 0; j < 8; j++) acc[i][j] += a[i] * b[j];
    }
}

// ---------------- GEMM1: Y = x @ [wq | wkv] + bias ------------------------
// grid (11, 512), block 256.  Writes q part -> g_q, kv part -> g_kvlin.
__global__ __launch_bounds__(256) void k_gemm1(
    const float* __restrict__ x,
    const float* __restrict__ wq,  const float* __restrict__ wqb,
    const float* __restrict__ wkv, const float* __restrict__ wkvb) {
    __shared__ float As[16][132];
    __shared__ float Bs[16][128];
    int tid = threadIdx.x;
    int m0 = blockIdx.y * 128;
    int n0 = blockIdx.x * 128;
    int tx = tid & 15, ty = tid >> 4;
    float acc[8][8] = {};

    for (int kt = 0; kt < C_; kt += 16) {
#pragma unroll
        for (int e = tid; e < 2048; e += 256) {
            int r = e >> 4, kk = e & 15;
            As[kk][r] = x[(size_t)(m0 + r) * C_ + kt + kk];
        }
#pragma unroll
        for (int e = tid; e < 2048; e += 256) {
            int kk = e >> 7, cc = e & 127;
            int n = n0 + cc;
            float bv;
            if (n < C_)         bv = wq[(size_t)(kt + kk) * C_ + n];
            else if (n < NCAT)  bv = wkv[(size_t)(kt + kk) * KV2 + (n - C_)];
            else                bv = 0.f;
            Bs[kk][cc] = bv;
        }
        __syncthreads();
        mma_tile<16>(As, Bs, acc, ty, tx);
        __syncthreads();
    }

#pragma unroll
    for (int i = 0; i < 8; i++) {
        int m = m0 + ty * 8 + i;
#pragma unroll
        for (int j = 0; j < 8; j++) {
            int n = n0 + tx * 8 + j;
            float v = acc[i][j];
            if (n < C_)
                g_q[(size_t)m * C_ + n] = v + wqb[n];
            else if (n < NCAT)
                g_kvlin[(size_t)m * KV2 + (n - C_)] = v + wkvb[n - C_];
        }
    }
}

// ---------------- block reduce two floats ----------------------------------
__device__ __forceinline__ void block_reduce2(float& s2, float& s6) {
#pragma unroll
    for (int o = 16; o; o >>= 1) {
        s2 += __shfl_down_sync(0xffffffffu, s2, o);
        s6 += __shfl_down_sync(0xffffffffu, s6, o);
    }
    __shared__ float sh2[8], sh6[8];
    int w = threadIdx.x >> 5, l = threadIdx.x & 31;
    if (l == 0) { sh2[w] = s2; sh6[w] = s6; }
    __syncthreads();
    if (threadIdx.x == 0) {
        float a = 0.f, c = 0.f;
#pragma unroll
        for (int i = 0; i < 8; i++) { a += sh2[i]; c += sh6[i]; }
        s2 = a; s6 = c;
    }
}

// ---------------- focused-norm reductions ----------------------------------
// grid 4096 = (bh 256) x (split 16); block 256
__global__ void k_qnorm() {
    int bh = blockIdx.x >> 4;
    int split = blockIdx.x & 15;
    int b = bh >> 4, h = bh & 15;
    const float* base = g_q + (size_t)(b * N_ + split * 256) * C_ + h * HD_;
    float s2 = 0.f, s6 = 0.f;
    for (int e = threadIdx.x; e < 256 * HD_; e += 256) {
        int r = e / HD_, d = e % HD_;
        float v = base[(size_t)r * C_ + d];
        float rr = fmaxf(v, 0.f);
        float r2 = rr * rr;  s2 += r2;
        float r3 = r2 * rr;  s6 += r3 * r3;
    }
    block_reduce2(s2, s6);
    if (threadIdx.x == 0) {
        atomicAdd(&g_qsum[bh * 2], s2);
        atomicAdd(&g_qsum[bh * 2 + 1], s6);
    }
}

// grid 256 = (b 16) x (split 16); block 256
__global__ void k_knorm() {
    int b = blockIdx.x >> 4;
    int split = blockIdx.x & 15;
    const float* base = g_kvlin + (size_t)(b * N_ + split * 256) * KV2;
    float s2 = 0.f, s6 = 0.f;
    for (int e = threadIdx.x; e < 256 * HD_; e += 256) {
        int r = e / HD_, d = e % HD_;
        float v = base[(size_t)r * KV2 + d];
        float rr = fmaxf(v, 0.f);
        float r2 = rr * rr;  s2 += r2;
        float r3 = r2 * rr;  s6 += r3 * r3;
    }
    block_reduce2(s2, s6);
    if (threadIdx.x == 0) {
        atomicAdd(&g_ksum[b * 2], s2);
        atomicAdd(&g_ksum[b * 2 + 1], s6);
    }
}

__global__ void k_scales() {
    int i = threadIdx.x;
    if (i < B_ * H_) {
        float s2 = g_qsum[i * 2], s6 = g_qsum[i * 2 + 1];
        g_scaleq[i] = (s6 > 0.f) ? sqrtf(s2 / s6) : 0.f;
    } else if (i < B_ * H_ + B_) {
        int b = i - B_ * H_;
        float s2 = g_ksum[b * 2], s6 = g_ksum[b * 2 + 1];
        g_scalek[b] = (s6 > 0.f) ? sqrtf(s2 / s6) : 0.f;
    }
}

// ---------------- kv = k_f^T @ v (per batch) --------------------------------
// grid (8 nsplits, 16 b), block 576; each thread owns 9 of 5184 outputs
__global__ __launch_bounds__(576) void k_kvacc() {
    __shared__ float ks[16][72], vs[16][72];
    int b = blockIdx.y;
    int n0 = blockIdx.x * 512;
    int tid = threadIdx.x;
    float acc[9] = {};
    int od[9], oe[9];
#pragma unroll
    for (int j = 0; j < 9; j++) { int o = tid + j * 576; od[j] = o / 72; oe[j] = o % 72; }

    for (int nt = 0; nt < 512; nt += 16) {
        __syncthreads();
        for (int e = tid; e < 16 * 72; e += 576) {
            int r = e / 72, d = e % 72;
            const float* p = g_kvlin + (size_t)(b * N_ + n0 + nt + r) * KV2;
            float kvv = p[d];
            float rr = fmaxf(kvv, 0.f);
            ks[r][d] = rr * rr * rr;
            vs[r][d] = p[72 + d];
        }
        __syncthreads();
#pragma unroll
        for (int r = 0; r < 16; r++)
#pragma unroll
            for (int j = 0; j < 9; j++) acc[j] += ks[r][od[j]] * vs[r][oe[j]];
    }
    float s = g_scalek[b];
#pragma unroll
    for (int j = 0; j < 9; j++)
        atomicAdd(&g_kv[b * 5184 + tid + j * 576], acc[j] * s);
}

// ---------------- depthwise 3x3 conv on v -----------------------------------
// grid 18432, block 256 (one thread per output element)
__global__ void k_dwc(const float* __restrict__ w, const float* __restrict__ bias) {
    int idx = blockIdx.x * blockDim.x + threadIdx.x;
    int d = idx % HD_;
    int t = idx / HD_;
    int n = t % N_;
    int b = t / N_;
    int y = n >> 6, xx = n & 63;
    float acc = bias[d];
#pragma unroll
    for (int ky = 0; ky < 3; ky++) {
        int yy = y + ky - 1;
        if ((unsigned)yy < 64u) {
#pragma unroll
            for (int kx = 0; kx < 3; kx++) {
                int xc = xx + kx - 1;
                if ((unsigned)xc < 64u)
                    acc += g_kvlin[(size_t)(b * N_ + yy * 64 + xc) * KV2 + 72 + d]
                         * w[d * 9 + ky * 3 + kx];
            }
        }
    }
    g_vd[(size_t)(b * N_ + n) * HD_ + d] = acc;
}

// ---------------- proj_sum[d][c] = sum_h proj[h*72+d][c] --------------------
// grid 324, block 256
__global__ void k_projsum(const float* __restrict__ proj) {
    int idx = blockIdx.x * blockDim.x + threadIdx.x;
    if (idx >= HD_ * C_) return;
    int d = idx / C_, c = idx % C_;
    float s = 0.f;
#pragma unroll
    for (int h = 0; h < H_; h++) s += proj[(size_t)(h * HD_ + d) * C_ + c];
    g_projsum[(size_t)d * C_ + c] = s;
}

// ---------------- M[b][h*72+d][c] = sum_e kv[b][d][e] * proj[h*72+e][c] -----
// grid (9 ctiles, 16 h, 16 b), block 256
__global__ __launch_bounds__(256) void k_mker(const float* __restrict__ proj) {
    __shared__ float kvs[72 * 72];
    int b = blockIdx.z, h = blockIdx.y, ct = blockIdx.x;
    int tid = threadIdx.x;
    for (int e = tid; e < 5184; e += 256) kvs[e] = g_kv[b * 5184 + e];
    __syncthreads();
    int c = ct * 128 + (tid & 127);
    int dbase = (tid >> 7) * 36;
    float acc[36] = {};
#pragma unroll 8
    for (int e2 = 0; e2 < 72; e2++) {
        float p = proj[(size_t)(h * HD_ + e2) * C_ + c];
#pragma unroll
        for (int dd = 0; dd < 36; dd++)
            acc[dd] += kvs[(dbase + dd) * 72 + e2] * p;
    }
#pragma unroll
    for (int dd = 0; dd < 36; dd++)
        g_M[(size_t)b * C_ * C_ + (size_t)(h * HD_ + dbase + dd) * C_ + c] = acc[dd];
}

// ---------------- GEMM2: out[b] = focused(q)[b]@M[b] + vd[b]@proj_sum + bias -
// grid (9, 32, 16), block 256
__global__ __launch_bounds__(256) void k_gemm2(const float* __restrict__ projb,
                                               float* __restrict__ out) {
    __shared__ float As[16][132];
    __shared__ float Bs[16][128];
    __shared__ float sq[16];
    int tid = threadIdx.x;
    int b = blockIdx.z;
    int m0 = blockIdx.y * 128;
    int n0 = blockIdx.x * 128;
    int tx = tid & 15, ty = tid >> 4;
    if (tid < 16) sq[tid] = g_scaleq[b * H_ + tid];
    __syncthreads();

    const float* qb = g_q + (size_t)b * N_ * C_;
    const float* Mb = g_M + (size_t)b * C_ * C_;
    float acc[8][8] = {};

    // phase 1: K = 1152 over focused(q) @ M[b]
    for (int kt = 0; kt < C_; kt += 16) {
#pragma unroll
        for (int e = tid; e < 2048; e += 256) {
            int r = e >> 4, kk = e & 15;
            int gk = kt + kk;
            int h = gk / 72;
            float v = qb[(size_t)(m0 + r) * C_ + gk];
            float rr = fmaxf(v, 0.f);
            As[kk][r] = sq[h] * rr * rr * rr;
        }
#pragma unroll
        for (int e = tid; e < 2048; e += 256) {
            int kk = e >> 7, cc = e & 127;
            Bs[kk][cc] = Mb[(size_t)(kt + kk) * C_ + n0 + cc];
        }
        __syncthreads();
        mma_tile<16>(As, Bs, acc, ty, tx);
        __syncthreads();
    }

    // phase 2: K = 72 over vd @ proj_sum
    const float* vdb = g_vd + (size_t)b * N_ * HD_;
    for (int kt = 0; kt < HD_; kt += 8) {
#pragma unroll
        for (int e = tid; e < 1024; e += 256) {
            int r = e >> 3, kk = e & 7;
            As[kk][r] = vdb[(size_t)(m0 + r) * HD_ + kt + kk];
        }
#pragma unroll
        for (int e = tid; e < 1024; e += 256) {
            int kk = e >> 7, cc = e & 127;
            Bs[kk][cc] = g_projsum[(size_t)(kt + kk) * C_ + n0 + cc];
        }
        __syncthreads();
        mma_tile<8>(As, Bs, acc, ty, tx);
        __syncthreads();
    }

#pragma unroll
    for (int i = 0; i < 8; i++) {
        int m = m0 + ty * 8 + i;
#pragma unroll
        for (int j = 0; j < 8; j++) {
            int n = n0 + tx * 8 + j;
            out[(size_t)(b * N_ + m) * C_ + n] = acc[i][j] + projb[n];
        }
    }
}

// ---------------- launch -----------------------------------------------------
extern "C" void kernel_launch(void* const* d_in, const int* in_sizes, int n_in,
                              void* d_out, int out_size) {
    const float* x      = (const float*)d_in[0];
    const float* wq_w   = (const float*)d_in[1];
    const float* wq_b   = (const float*)d_in[2];
    const float* wkv_w  = (const float*)d_in[3];
    const float* wkv_b  = (const float*)d_in[4];
    const float* dwc_w  = (const float*)d_in[5];
    const float* dwc_b  = (const float*)d_in[6];
    const float* proj_w = (const float*)d_in[7];
    const float* proj_b = (const float*)d_in[8];
    float* out = (float*)d_out;

    k_init<<<324, 256>>>();
    k_gemm1<<<dim3(11, 512), 256>>>(x, wq_w, wq_b, wkv_w, wkv_b);
    k_qnorm<<<4096, 256>>>();
    k_knorm<<<256, 256>>>();
    k_scales<<<1, 288>>>();
    k_kvacc<<<dim3(8, 16), 576>>>();
    k_dwc<<<18432, 256>>>(dwc_w, dwc_b);
    k_projsum<<<324, 256>>>(proj_w);
    k_mker<<<dim3(9, 16, 16), 256>>>(proj_w);
    k_gemm2<<<dim3(9, 32, 16), 256>>>(proj_b, out);
}

// round 3
// speedup vs baseline: 1.0032x; 1.0027x over previous
#include <cuda_runtime.h>
#include <math.h>

#define B_   16
#define N_   4096
#define C_   1152
#define H_   16
#define HD_  72
#define KV2  144          // 2*HD
#define NCAT 1296         // C_ + KV2
#define MTOT (B_*N_)      // 65536

// ---------------- scratch (static device globals; no runtime alloc) -------
__device__ float g_q[(size_t)MTOT * C_];        // 302 MB  q = x@wq + b
__device__ float g_kvlin[(size_t)MTOT * KV2];   // 37.7 MB [k|v]
__device__ float g_vd[(size_t)MTOT * HD_];      // 18.9 MB depthwise conv out
__device__ float g_kv[B_ * HD_ * HD_];          // kv = k_f^T @ v  (per batch)
__device__ float g_M[(size_t)B_ * C_ * C_];     // 85 MB  blockdiag(kv)@proj
__device__ float g_projsum[HD_ * C_];           // sum_h proj rows
__device__ float g_qsum[B_ * H_ * 2];           // {sum r^2, sum r^6} per (b,h)
__device__ float g_ksum[B_ * 2];                // per b
__device__ float g_scaleq[B_ * H_];
__device__ float g_scalek[B_];

// ---------------- init: zero accumulators ---------------------------------
__global__ void k_init() {
    int i = blockIdx.x * blockDim.x + threadIdx.x;
    if (i < B_ * HD_ * HD_) g_kv[i] = 0.f;
    if (i < B_ * H_ * 2)    g_qsum[i] = 0.f;
    if (i < B_ * 2)         g_ksum[i] = 0.f;
}

// ---------------- shared GEMM micro-kernel --------------------------------
template <int KK>
__device__ __forceinline__ void mma_tile(const float As[16][132],
                                         const float Bs[16][128],
                                         float (&acc)[8][8], int ty, int tx) {
#pragma unroll
    for (int k = 0; k < KK; k++) {
        float4 a0 = *(const float4*)&As[k][ty * 8];
        float4 a1 = *(const float4*)&As[k][ty * 8 + 4];
        float4 b0 = *(const float4*)&Bs[k][tx * 8];
        float4 b1 = *(const float4*)&Bs[k][tx * 8 + 4];
        float a[8] = {a0.x, a0.y, a0.z, a0.w, a1.x, a1.y, a1.z, a1.w};
        float b[8] = {b0.x, b0.y, b0.z, b0.w, b1.x, b1.y, b1.z, b1.w};
#pragma unroll
        for (int i = 0; i < 8; i++)
#pragma unroll
            for (int j = 0; j < 8; j++) acc[i][j] += a[i] * b[j];
    }
}

// ---------------- GEMM1: Y = x @ [wq | wkv] + bias ------------------------
// grid (11, 512), block 256.  Writes q part -> g_q, kv part -> g_kvlin.
__global__ __launch_bounds__(256) void k_gemm1(
    const float* __restrict__ x,
    const float* __restrict__ wq,  const float* __restrict__ wqb,
    const float* __restrict__ wkv, const float* __restrict__ wkvb) {
    __shared__ float As[16][132];
    __shared__ float Bs[16][128];
    int tid = threadIdx.x;
    int m0 = blockIdx.y * 128;
    int n0 = blockIdx.x * 128;
    int tx = tid & 15, ty = tid >> 4;
    float acc[8][8] = {};

    for (int kt = 0; kt < C_; kt += 16) {
#pragma unroll
        for (int e = tid; e < 2048; e += 256) {
            int r = e >> 4, kk = e & 15;
            As[kk][r] = x[(size_t)(m0 + r) * C_ + kt + kk];
        }
#pragma unroll
        for (int e = tid; e < 2048; e += 256) {
            int kk = e >> 7, cc = e & 127;
            int n = n0 + cc;
            float bv;
            if (n < C_)         bv = wq[(size_t)(kt + kk) * C_ + n];
            else if (n < NCAT)  bv = wkv[(size_t)(kt + kk) * KV2 + (n - C_)];
            else                bv = 0.f;
            Bs[kk][cc] = bv;
        }
        __syncthreads();
        mma_tile<16>(As, Bs, acc, ty, tx);
        __syncthreads();
    }

#pragma unroll
    for (int i = 0; i < 8; i++) {
        int m = m0 + ty * 8 + i;
#pragma unroll
        for (int j = 0; j < 8; j++) {
            int n = n0 + tx * 8 + j;
            float v = acc[i][j];
            if (n < C_)
                g_q[(size_t)m * C_ + n] = v + wqb[n];
            else if (n < NCAT)
                g_kvlin[(size_t)m * KV2 + (n - C_)] = v + wkvb[n - C_];
        }
    }
}

// ---------------- block reduce two floats ----------------------------------
__device__ __forceinline__ void block_reduce2(float& s2, float& s6) {
#pragma unroll
    for (int o = 16; o; o >>= 1) {
        s2 += __shfl_down_sync(0xffffffffu, s2, o);
        s6 += __shfl_down_sync(0xffffffffu, s6, o);
    }
    __shared__ float sh2[8], sh6[8];
    int w = threadIdx.x >> 5, l = threadIdx.x & 31;
    if (l == 0) { sh2[w] = s2; sh6[w] = s6; }
    __syncthreads();
    if (threadIdx.x == 0) {
        float a = 0.f, c = 0.f;
#pragma unroll
        for (int i = 0; i < 8; i++) { a += sh2[i]; c += sh6[i]; }
        s2 = a; s6 = c;
    }
}

// ---------------- focused-norm reductions ----------------------------------
// grid 4096 = (bh 256) x (split 16); block 256
__global__ void k_qnorm() {
    int bh = blockIdx.x >> 4;
    int split = blockIdx.x & 15;
    int b = bh >> 4, h = bh & 15;
    const float* base = g_q + (size_t)(b * N_ + split * 256) * C_ + h * HD_;
    float s2 = 0.f, s6 = 0.f;
    for (int e = threadIdx.x; e < 256 * HD_; e += 256) {
        int r = e / HD_, d = e % HD_;
        float v = base[(size_t)r * C_ + d];
        float rr = fmaxf(v, 0.f);
        float r2 = rr * rr;  s2 += r2;
        float r3 = r2 * rr;  s6 += r3 * r3;
    }
    block_reduce2(s2, s6);
    if (threadIdx.x == 0) {
        atomicAdd(&g_qsum[bh * 2], s2);
        atomicAdd(&g_qsum[bh * 2 + 1], s6);
    }
}

// grid 256 = (b 16) x (split 16); block 256
__global__ void k_knorm() {
    int b = blockIdx.x >> 4;
    int split = blockIdx.x & 15;
    const float* base = g_kvlin + (size_t)(b * N_ + split * 256) * KV2;
    float s2 = 0.f, s6 = 0.f;
    for (int e = threadIdx.x; e < 256 * HD_; e += 256) {
        int r = e / HD_, d = e % HD_;
        float v = base[(size_t)r * KV2 + d];
        float rr = fmaxf(v, 0.f);
        float r2 = rr * rr;  s2 += r2;
        float r3 = r2 * rr;  s6 += r3 * r3;
    }
    block_reduce2(s2, s6);
    if (threadIdx.x == 0) {
        atomicAdd(&g_ksum[b * 2], s2);
        atomicAdd(&g_ksum[b * 2 + 1], s6);
    }
}

__global__ void k_scales() {
    int i = threadIdx.x;
    if (i < B_ * H_) {
        float s2 = g_qsum[i * 2], s6 = g_qsum[i * 2 + 1];
        g_scaleq[i] = (s6 > 0.f) ? sqrtf(s2 / s6) : 0.f;
    } else if (i < B_ * H_ + B_) {
        int b = i - B_ * H_;
        float s2 = g_ksum[b * 2], s6 = g_ksum[b * 2 + 1];
        g_scalek[b] = (s6 > 0.f) ? sqrtf(s2 / s6) : 0.f;
    }
}

// ---------------- kv = k_f^T @ v (per batch) --------------------------------
// grid (8 nsplits, 16 b), block 576; each thread owns 9 of 5184 outputs
__global__ __launch_bounds__(576) void k_kvacc() {
    __shared__ float ks[16][72], vs[16][72];
    int b = blockIdx.y;
    int n0 = blockIdx.x * 512;
    int tid = threadIdx.x;
    float acc[9] = {};
    int od[9], oe[9];
#pragma unroll
    for (int j = 0; j < 9; j++) { int o = tid + j * 576; od[j] = o / 72; oe[j] = o % 72; }

    for (int nt = 0; nt < 512; nt += 16) {
        __syncthreads();
        for (int e = tid; e < 16 * 72; e += 576) {
            int r = e / 72, d = e % 72;
            const float* p = g_kvlin + (size_t)(b * N_ + n0 + nt + r) * KV2;
            float kvv = p[d];
            float rr = fmaxf(kvv, 0.f);
            ks[r][d] = rr * rr * rr;
            vs[r][d] = p[72 + d];
        }
        __syncthreads();
#pragma unroll
        for (int r = 0; r < 16; r++)
#pragma unroll
            for (int j = 0; j < 9; j++) acc[j] += ks[r][od[j]] * vs[r][oe[j]];
    }
    float s = g_scalek[b];
#pragma unroll
    for (int j = 0; j < 9; j++)
        atomicAdd(&g_kv[b * 5184 + tid + j * 576], acc[j] * s);
}

// ---------------- depthwise 3x3 conv on v -----------------------------------
// grid 18432, block 256 (one thread per output element)
__global__ void k_dwc(const float* __restrict__ w, const float* __restrict__ bias) {
    int idx = blockIdx.x * blockDim.x + threadIdx.x;
    int d = idx % HD_;
    int t = idx / HD_;
    int n = t % N_;
    int b = t / N_;
    int y = n >> 6, xx = n & 63;
    float acc = bias[d];
#pragma unroll
    for (int ky = 0; ky < 3; ky++) {
        int yy = y + ky - 1;
        if ((unsigned)yy < 64u) {
#pragma unroll
            for (int kx = 0; kx < 3; kx++) {
                int xc = xx + kx - 1;
                if ((unsigned)xc < 64u)
                    acc += g_kvlin[(size_t)(b * N_ + yy * 64 + xc) * KV2 + 72 + d]
                         * w[d * 9 + ky * 3 + kx];
            }
        }
    }
    g_vd[(size_t)(b * N_ + n) * HD_ + d] = acc;
}

// ---------------- proj_sum[d][c] = sum_h proj[h*72+d][c] --------------------
// grid 324, block 256
__global__ void k_projsum(const float* __restrict__ proj) {
    int idx = blockIdx.x * blockDim.x + threadIdx.x;
    if (idx >= HD_ * C_) return;
    int d = idx / C_, c = idx % C_;
    float s = 0.f;
#pragma unroll
    for (int h = 0; h < H_; h++) s += proj[(size_t)(h * HD_ + d) * C_ + c];
    g_projsum[(size_t)d * C_ + c] = s;
}

// ---------------- M[b][h*72+d][c] = sum_e kv[b][d][e] * proj[h*72+e][c] -----
// grid (9 ctiles, 16 h, 16 b), block 256
__global__ __launch_bounds__(256) void k_mker(const float* __restrict__ proj) {
    __shared__ float kvs[72 * 72];
    int b = blockIdx.z, h = blockIdx.y, ct = blockIdx.x;
    int tid = threadIdx.x;
    for (int e = tid; e < 5184; e += 256) kvs[e] = g_kv[b * 5184 + e];
    __syncthreads();
    int c = ct * 128 + (tid & 127);
    int dbase = (tid >> 7) * 36;
    float acc[36] = {};
#pragma unroll 8
    for (int e2 = 0; e2 < 72; e2++) {
        float p = proj[(size_t)(h * HD_ + e2) * C_ + c];
#pragma unroll
        for (int dd = 0; dd < 36; dd++)
            acc[dd] += kvs[(dbase + dd) * 72 + e2] * p;
    }
#pragma unroll
    for (int dd = 0; dd < 36; dd++)
        g_M[(size_t)b * C_ * C_ + (size_t)(h * HD_ + dbase + dd) * C_ + c] = acc[dd];
}

// ---------------- GEMM2: out[b] = focused(q)[b]@M[b] + vd[b]@proj_sum + bias -
// grid (9, 32, 16), block 256
__global__ __launch_bounds__(256) void k_gemm2(const float* __restrict__ projb,
                                               float* __restrict__ out) {
    __shared__ float As[16][132];
    __shared__ float Bs[16][128];
    __shared__ float sq[16];
    int tid = threadIdx.x;
    int b = blockIdx.z;
    int m0 = blockIdx.y * 128;
    int n0 = blockIdx.x * 128;
    int tx = tid & 15, ty = tid >> 4;
    if (tid < 16) sq[tid] = g_scaleq[b * H_ + tid];
    __syncthreads();

    const float* qb = g_q + (size_t)b * N_ * C_;
    const float* Mb = g_M + (size_t)b * C_ * C_;
    float acc[8][8] = {};

    // phase 1: K = 1152 over focused(q) @ M[b]
    for (int kt = 0; kt < C_; kt += 16) {
#pragma unroll
        for (int e = tid; e < 2048; e += 256) {
            int r = e >> 4, kk = e & 15;
            int gk = kt + kk;
            int h = gk / 72;
            float v = qb[(size_t)(m0 + r) * C_ + gk];
            float rr = fmaxf(v, 0.f);
            As[kk][r] = sq[h] * rr * rr * rr;
        }
#pragma unroll
        for (int e = tid; e < 2048; e += 256) {
            int kk = e >> 7, cc = e & 127;
            Bs[kk][cc] = Mb[(size_t)(kt + kk) * C_ + n0 + cc];
        }
        __syncthreads();
        mma_tile<16>(As, Bs, acc, ty, tx);
        __syncthreads();
    }

    // phase 2: K = 72 over vd @ proj_sum
    const float* vdb = g_vd + (size_t)b * N_ * HD_;
    for (int kt = 0; kt < HD_; kt += 8) {
#pragma unroll
        for (int e = tid; e < 1024; e += 256) {
            int r = e >> 3, kk = e & 7;
            As[kk][r] = vdb[(size_t)(m0 + r) * HD_ + kt + kk];
        }
#pragma unroll
        for (int e = tid; e < 1024; e += 256) {
            int kk = e >> 7, cc = e & 127;
            Bs[kk][cc] = g_projsum[(size_t)(kt + kk) * C_ + n0 + cc];
        }
        __syncthreads();
        mma_tile<8>(As, Bs, acc, ty, tx);
        __syncthreads();
    }

#pragma unroll
    for (int i = 0; i < 8; i++) {
        int m = m0 + ty * 8 + i;
#pragma unroll
        for (int j = 0; j < 8; j++) {
            int n = n0 + tx * 8 + j;
            out[(size_t)(b * N_ + m) * C_ + n] = acc[i][j] + projb[n];
        }
    }
}

// ---------------- launch -----------------------------------------------------
extern "C" void kernel_launch(void* const* d_in, const int* in_sizes, int n_in,
                              void* d_out, int out_size) {
    const float* x      = (const float*)d_in[0];
    const float* wq_w   = (const float*)d_in[1];
    const float* wq_b   = (const float*)d_in[2];
    const float* wkv_w  = (const float*)d_in[3];
    const float* wkv_b  = (const float*)d_in[4];
    const float* dwc_w  = (const float*)d_in[5];
    const float* dwc_b  = (const float*)d_in[6];
    const float* proj_w = (const float*)d_in[7];
    const float* proj_b = (const float*)d_in[8];
    float* out = (float*)d_out;

    k_init<<<324, 256>>>();
    k_gemm1<<<dim3(11, 512), 256>>>(x, wq_w, wq_b, wkv_w, wkv_b);
    k_qnorm<<<4096, 256>>>();
    k_knorm<<<256, 256>>>();
    k_scales<<<1, 288>>>();
    k_kvacc<<<dim3(8, 16), 576>>>();
    k_dwc<<<18432, 256>>>(dwc_w, dwc_b);
    k_projsum<<<324, 256>>>(proj_w);
    k_mker<<<dim3(9, 16, 16), 256>>>(proj_w);
    k_gemm2<<<dim3(9, 32, 16), 256>>>(proj_b, out);
}